// round 1
// baseline (speedup 1.0000x reference)
#include <cuda_runtime.h>
#include <math.h>

#define DD 512          // transition steps
#define NN 256          // batch
#define HH 128          // h_dim
#define LL 64           // label dim
#define KDIM 320        // L + 2H
#define NGATE 5
#define MT 16           // batch rows per CTA
#define HT 16           // h units per CTA
#define NMT (NN / MT)   // 16 M-tiles
#define NHG (HH / HT)   // 8 h-groups
#define GRID (NMT * NHG) // 128 CTAs
#define THREADS 256
#define XSTR 324        // padded X row stride in floats (bank-friendly, 16B-aligned)
#define KSTR 324        // padded W k-stride in floats

// ---- device scratch (static module allocations, the sanctioned path) ----
__device__ float g_hst[(long)DD * NN * HH];   // h stack  [D][N][H]
__device__ float g_cst[(long)DD * NN * HH];   // c stack  [D][N][H]
__device__ unsigned g_cnt[NMT];               // per-M-tile barrier counters (monotonic)

__device__ __forceinline__ float sigf(float x) { return 1.0f / (1.0f + expf(-x)); }

// dynamic smem layout (bytes):
//   Wsm   : 5*16*KSTR floats          = 103680
//   Xsm   : MT*XSTR floats            =  20736
//   bsm   : 80 floats                 =    320
//   ints  : mask/lidx/ridx/lab/sp 5x16=    320
//   stack : MT*DD ushort              =  16384
#define WSM_F   (NGATE * HT * KSTR)
#define XSM_F   (MT * XSTR)
#define SMEM_BYTES (WSM_F*4 + XSM_F*4 + 80*4 + 5*MT*4 + MT*DD*2 + 64)

__global__ void __launch_bounds__(THREADS, 1) spinn_persistent(
    const int*   __restrict__ trans,     // [D][N]
    const int*   __restrict__ labels,    // [D][N]
    const float* __restrict__ emb,       // [V][L]
    const float* __restrict__ W,         // [320][640]
    const float* __restrict__ b,         // [640]
    const float* __restrict__ leaf,      // [128]
    float*       __restrict__ out)       // [2][N][H]  (c then h)
{
    extern __shared__ float sm[];
    float* Wsm = sm;                               // [5][HT][KSTR]
    float* Xsm = sm + WSM_F;                       // [MT][XSTR]
    float* bsm = Xsm + XSM_F;                      // [80]
    int*   ri_m   = (int*)(bsm + 80);              // [MT] mask
    int*   ri_l   = ri_m + MT;                     // [MT] lidx
    int*   ri_r   = ri_l + MT;                     // [MT] ridx
    int*   ri_lab = ri_r + MT;                     // [MT] label idx
    int*   ssp    = ri_lab + MT;                   // [MT] stack ptr
    unsigned short* stk = (unsigned short*)(ssp + MT); // [MT][DD]

    const int tid = threadIdx.x;
    const int ci  = blockIdx.x;
    const int mt  = ci >> 3;          // M-tile 0..15
    const int hg  = ci & 7;           // h-group 0..7
    const int n0  = mt * MT;
    const int h0  = hg * HT;
    const int row = tid & 15;         // batch row within tile
    const int hc  = tid >> 4;         // h unit within tile (0..15)

    // ---- one-time: load W slice + bias slice into smem ----
    for (int e = tid; e < NGATE * HT * KDIM; e += THREADS) {
        int k = e % KDIM;
        int c = e / KDIM;             // c = g*HT + hcc
        int g = c >> 4, hcc = c & 15;
        Wsm[(g * HT + hcc) * KSTR + k] = W[(long)k * (NGATE * HH) + g * HH + h0 + hcc];
    }
    if (tid < NGATE * HT) {
        int g = tid >> 4, hcc = tid & 15;
        bsm[tid] = b[g * HH + h0 + hcc];
    }
    if (tid < MT) ssp[tid] = 0;
    __syncthreads();

    const float4* Xs4 = (const float4*)Xsm;
    const float4* Ws4 = (const float4*)Wsm;

    for (int t = 0; t < DD; ++t) {
        // ---- stack simulation + row info (threads 0..15) ----
        if (tid < MT) {
            int n = n0 + tid;
            int m = trans[t * NN + n];
            ri_lab[tid] = labels[t * NN + n];
            int sp = ssp[tid];
            int li = 0, rx = 0;
            if (m) { rx = stk[tid * DD + sp - 1]; li = stk[tid * DD + sp - 2]; }
            ri_m[tid] = m; ri_l[tid] = li; ri_r[tid] = rx;
            int np = sp - 2 * m;
            stk[tid * DD + np] = (unsigned short)t;
            ssp[tid] = np + 1;
        }
        __syncthreads();

        // ---- gather X = [label(64) | hl(128) | hr(128)] into smem ----
        for (int e = tid; e < MT * LL; e += THREADS) {       // label embedding
            int r = e >> 6, k = e & 63;
            Xsm[r * XSTR + k] = emb[(long)ri_lab[r] * LL + k];
        }
        for (int e = tid; e < MT * HH; e += THREADS) {       // h_left
            int r = e >> 7, k = e & 127;
            float v = ri_m[r] ? __ldcg(&g_hst[((long)ri_l[r] * NN + n0 + r) * HH + k])
                              : leaf[k];
            Xsm[r * XSTR + LL + k] = v;
        }
        for (int e = tid; e < MT * HH; e += THREADS) {       // h_right
            int r = e >> 7, k = e & 127;
            float v = ri_m[r] ? __ldcg(&g_hst[((long)ri_r[r] * NN + n0 + r) * HH + k])
                              : leaf[k];
            Xsm[r * XSTR + LL + HH + k] = v;
        }
        __syncthreads();

        // ---- GEMM: this thread computes 5 gate dots for (row, hc) ----
        float a0 = 0.f, a1 = 0.f, a2 = 0.f, a3 = 0.f, a4 = 0.f;
        const float4* xr = Xs4 + row * (XSTR / 4);
        const int w0i = (0 * HT + hc) * (KSTR / 4);
        const int w1i = (1 * HT + hc) * (KSTR / 4);
        const int w2i = (2 * HT + hc) * (KSTR / 4);
        const int w3i = (3 * HT + hc) * (KSTR / 4);
        const int w4i = (4 * HT + hc) * (KSTR / 4);
        #pragma unroll 4
        for (int k4 = 0; k4 < KDIM / 4; ++k4) {
            float4 x = xr[k4];
            float4 w;
            w = Ws4[w0i + k4]; a0 += x.x*w.x + x.y*w.y + x.z*w.z + x.w*w.w;
            w = Ws4[w1i + k4]; a1 += x.x*w.x + x.y*w.y + x.z*w.z + x.w*w.w;
            w = Ws4[w2i + k4]; a2 += x.x*w.x + x.y*w.y + x.z*w.z + x.w*w.w;
            w = Ws4[w3i + k4]; a3 += x.x*w.x + x.y*w.y + x.z*w.z + x.w*w.w;
            w = Ws4[w4i + k4]; a4 += x.x*w.x + x.y*w.y + x.z*w.z + x.w*w.w;
        }

        // ---- gates + cell update ----
        {
            int n = n0 + row;
            int h = h0 + hc;
            int m = ri_m[row];
            float cl = m ? __ldcg(&g_cst[((long)ri_l[row] * NN + n) * HH + h]) : leaf[h];
            float cr = m ? __ldcg(&g_cst[((long)ri_r[row] * NN + n) * HH + h]) : leaf[h];
            float gi = a0 + bsm[hc];
            float gl = a1 + bsm[HT + hc];
            float gr = a2 + bsm[2 * HT + hc];
            float go = a3 + bsm[3 * HT + hc];
            float gu = a4 + bsm[4 * HT + hc];
            float c  = sigf(gi) * tanhf(gu) + sigf(gl) * cl + sigf(gr) * cr;
            float hv = sigf(go) * tanhf(c);
            long off = ((long)t * NN + n) * HH + h;
            g_cst[off] = c;
            g_hst[off] = hv;
            if (t == DD - 1) {
                out[n * HH + h] = c;                  // c_st[D-1] first
                out[NN * HH + n * HH + h] = hv;       // then h_st[D-1]
            }
        }

        // ---- 8-CTA barrier for this M-tile group (monotonic, replay-safe) ----
        __syncthreads();
        if (tid == 0) {
            __threadfence();
            unsigned a = atomicAdd(&g_cnt[mt], 1u) + 1u;
            unsigned tgt = (a + 7u) & ~7u;    // counter starts each replay ≡ 0 (mod 8)
            unsigned v;
            do {
                asm volatile("ld.global.acquire.gpu.u32 %0, [%1];"
                             : "=r"(v) : "l"(&g_cnt[mt]));
            } while (v < tgt);
        }
        __syncthreads();
    }
}

extern "C" void kernel_launch(void* const* d_in, const int* in_sizes, int n_in,
                              void* d_out, int out_size)
{
    const int*   trans  = (const int*)  d_in[0];
    const int*   labels = (const int*)  d_in[1];
    const float* emb    = (const float*)d_in[2];
    const float* W      = (const float*)d_in[3];
    const float* b      = (const float*)d_in[4];
    const float* leaf   = (const float*)d_in[5];
    float*       out    = (float*)d_out;

    cudaFuncSetAttribute(spinn_persistent,
                         cudaFuncAttributeMaxDynamicSharedMemorySize, SMEM_BYTES);
    spinn_persistent<<<GRID, THREADS, SMEM_BYTES>>>(trans, labels, emb, W, b, leaf, out);
}

// round 3
// speedup vs baseline: 1.4081x; 1.4081x over previous
#include <cuda_runtime.h>
#include <math.h>

#define DD 512          // transition steps
#define NN 256          // batch
#define HH 128          // h_dim
#define LL 64           // label dim
#define KDIM 320        // L + 2H
#define NGATE 5
#define MT 16           // batch rows per CTA
#define HT 16           // h units per CTA
#define NMT (NN / MT)   // 16 M-tiles
#define NHG (HH / HT)   // 8 h-groups
#define GRID (NMT * NHG) // 128 CTAs
#define THREADS 256

#define WSM_F 25600       // 80 k4 * 5 g * 8 hcp * 8 floats
#define XROW  660         // padded X row stride in floats (dup layout: 640 used)
#define XSM_F (MT * XROW) // 10560 floats

// ---- device scratch (static module allocations, the sanctioned path) ----
__device__ float g_hst[(long)DD * NN * HH];   // h stack  [D][N][H]
__device__ float g_cst[(long)DD * NN * HH];   // c stack  [D][N][H]
__device__ unsigned g_cnt[NMT];               // per-M-tile barrier counters (monotonic)

__device__ __forceinline__ float sigf(float x) { return 1.0f / (1.0f + expf(-x)); }

// packed fp32x2 FMA (Blackwell FFMA2 — only reachable via PTX)
#define FMA2(d, a, b) asm("fma.rn.f32x2 %0, %1, %2, %0;" : "+l"(d) : "l"(a), "l"(b))

#define SMEM_BYTES ((WSM_F + XSM_F + 80 + 128) * 4 + 5 * MT * 4 + MT * DD * 2 + 64)

__global__ void __launch_bounds__(THREADS, 1) spinn_persistent(
    const int*   __restrict__ trans,     // [D][N]
    const int*   __restrict__ labels,    // [D][N]
    const float* __restrict__ emb,       // [V][L]
    const float* __restrict__ W,         // [320][640]
    const float* __restrict__ b,         // [640]
    const float* __restrict__ leaf,      // [128]
    float*       __restrict__ out)       // [2][N][H]  (c then h)
{
    extern __shared__ float sm[];
    float* Wsm = sm;                               // [80 k4][5 g][8 hcp][8]
    float* Xsm = sm + WSM_F;                       // dup layout [16 rows][660]
    float* bsm = Xsm + XSM_F;                      // [80]
    float* Lsm = bsm + 80;                         // [128] leaf cache
    int*   ri_m   = (int*)(Lsm + 128);             // [MT] mask
    int*   ri_l   = ri_m + MT;                     // [MT] lidx
    int*   ri_r   = ri_l + MT;                     // [MT] ridx
    int*   ri_lab = ri_r + MT;                     // [MT] label idx
    int*   ssp    = ri_lab + MT;                   // [MT] stack ptr
    unsigned short* stk = (unsigned short*)(ssp + MT); // [MT][DD]

    const int tid = threadIdx.x;
    const int ci  = blockIdx.x;
    const int mt  = ci >> 3;          // M-tile 0..15
    const int hg  = ci & 7;           // h-group 0..7
    const int n0  = mt * MT;
    const int h0  = hg * HT;
    const int row = tid & 15;         // epilogue: batch row within tile
    const int hc  = tid >> 4;         // epilogue: h unit within tile (0..15)

    // GEMM thread geometry: rp = row-pair, hq = hc-pair, ks = k-split
    const int rp = tid & 7;           // 0..7  -> rows 2rp, 2rp+1
    const int hq = (tid >> 3) & 7;    // 0..7  -> hc 2hq, 2hq+1
    const int ks = tid >> 6;          // 0..3  -> k4 in [ks*20, ks*20+20)

    // ---- one-time: W relayout into smem ----
    // Wsm[((k4*5+g)*8+hcp)*8 + kk*2 + lane] = W[(k4*4+kk)*640 + g*128 + h0 + hcp*2 + lane]
    for (int e = tid; e < WSM_F; e += THREADS) {
        int lane = e & 1;
        int kk   = (e >> 1) & 3;
        int hcp  = (e >> 3) & 7;
        int g    = (e >> 6) % 5;
        int k4   = e / 320;
        Wsm[e] = W[(long)(k4 * 4 + kk) * (NGATE * HH) + g * HH + h0 + hcp * 2 + lane];
    }
    if (tid < NGATE * HT) {
        int g = tid >> 4, hcc = tid & 15;
        bsm[tid] = b[g * HH + h0 + hcc];
    }
    if (tid < HH) Lsm[tid] = leaf[tid];
    if (tid < MT) ssp[tid] = 0;
    __syncthreads();

    for (int t = 0; t < DD; ++t) {
        // ---- stack simulation + row info (threads 0..15) ----
        if (tid < MT) {
            int n = n0 + tid;
            int m = trans[t * NN + n];
            ri_lab[tid] = labels[t * NN + n];
            int sp = ssp[tid];
            int li = 0, rx = 0;
            if (m) { rx = stk[tid * DD + sp - 1]; li = stk[tid * DD + sp - 2]; }
            ri_m[tid] = m; ri_l[tid] = li; ri_r[tid] = rx;
            int np = sp - 2 * m;
            stk[tid * DD + np] = (unsigned short)t;
            ssp[tid] = np + 1;
        }
        __syncthreads();

        // ---- gather X (value-duplicated float2) = [label|hl|hr] ----
        {
            float2* X2 = (float2*)Xsm;
            for (int e = tid; e < MT * LL; e += THREADS) {       // label embedding
                int r = e >> 6, k = e & 63;
                float v = emb[(long)ri_lab[r] * LL + k];
                X2[r * (XROW / 2) + k] = make_float2(v, v);
            }
            for (int e = tid; e < MT * HH; e += THREADS) {       // h_left
                int r = e >> 7, k = e & 127;
                float v = ri_m[r] ? __ldcg(&g_hst[((long)ri_l[r] * NN + n0 + r) * HH + k])
                                  : Lsm[k];
                X2[r * (XROW / 2) + LL + k] = make_float2(v, v);
            }
            for (int e = tid; e < MT * HH; e += THREADS) {       // h_right
                int r = e >> 7, k = e & 127;
                float v = ri_m[r] ? __ldcg(&g_hst[((long)ri_r[r] * NN + n0 + r) * HH + k])
                                  : Lsm[k];
                X2[r * (XROW / 2) + LL + HH + k] = make_float2(v, v);
            }
        }
        __syncthreads();

        // ---- GEMM slice: 2 rows x 5 gates x (2 hc packed), k in [ks*80, ks*80+80) ----
        long long acc[10];
        #pragma unroll
        for (int a = 0; a < 10; ++a) acc[a] = 0;   // f32x2 (0.0f, 0.0f)

        const longlong2* Xr0 = (const longlong2*)(Xsm + (2 * rp)     * XROW);
        const longlong2* Xr1 = (const longlong2*)(Xsm + (2 * rp + 1) * XROW);
        const int k4base = ks * 20;

        #pragma unroll 2
        for (int i = 0; i < 20; ++i) {
            int k4 = k4base + i;
            longlong2 xa0 = Xr0[k4 * 2];       // dup(x_k0), dup(x_k1)  (row A)
            longlong2 xa1 = Xr0[k4 * 2 + 1];   // dup(x_k2), dup(x_k3)
            longlong2 xb0 = Xr1[k4 * 2];
            longlong2 xb1 = Xr1[k4 * 2 + 1];
            const float* wb = Wsm + k4 * 320 + hq * 8;
            #pragma unroll
            for (int g = 0; g < 5; ++g) {
                longlong2 w01 = *(const longlong2*)(wb + g * 64);       // (h0,h1)@k0, @k1
                longlong2 w23 = *(const longlong2*)(wb + g * 64 + 4);   // (h0,h1)@k2, @k3
                FMA2(acc[g],     xa0.x, w01.x);
                FMA2(acc[g],     xa0.y, w01.y);
                FMA2(acc[g],     xa1.x, w23.x);
                FMA2(acc[g],     xa1.y, w23.y);
                FMA2(acc[5 + g], xb0.x, w01.x);
                FMA2(acc[5 + g], xb0.y, w01.y);
                FMA2(acc[5 + g], xb1.x, w23.x);
                FMA2(acc[5 + g], xb1.y, w23.y);
            }
        }
        __syncthreads();   // all X reads done; reuse X region for partials

        // ---- write k-split partials: Red[ks][rp][hq][10] (f32x2) ----
        {
            long long* Red = (long long*)Xsm;
            long long* dst = Red + (((ks * 8 + rp) * 8 + hq) * 10);
            #pragma unroll
            for (int a = 0; a < 10; ++a) dst[a] = acc[a];
        }
        __syncthreads();

        // ---- reduce + gates + cell update: thread = (row, hc) ----
        {
            const float* Redf = Xsm;
            // partial float idx = ks*1280 + ((rp*8+hq)*10 + r*5 + g)*2 + lane
            const int base0 = (((row >> 1) * 8 + (hc >> 1)) * 10 + (row & 1) * 5) * 2 + (hc & 1);
            float gate[5];
            #pragma unroll
            for (int g = 0; g < 5; ++g) {
                int f = base0 + g * 2;
                gate[g] = Redf[f] + Redf[f + 1280] + Redf[f + 2560] + Redf[f + 3840]
                        + bsm[g * HT + hc];
            }
            int n = n0 + row;
            int h = h0 + hc;
            int m = ri_m[row];
            float cl = m ? __ldcg(&g_cst[((long)ri_l[row] * NN + n) * HH + h]) : Lsm[h];
            float cr = m ? __ldcg(&g_cst[((long)ri_r[row] * NN + n) * HH + h]) : Lsm[h];
            float c  = sigf(gate[0]) * tanhf(gate[4]) + sigf(gate[1]) * cl + sigf(gate[2]) * cr;
            float hv = sigf(gate[3]) * tanhf(c);
            long off = ((long)t * NN + n) * HH + h;
            g_cst[off] = c;
            g_hst[off] = hv;
            if (t == DD - 1) {
                out[n * HH + h] = c;                  // c_st[D-1] first
                out[NN * HH + n * HH + h] = hv;       // then h_st[D-1]
            }
        }

        // ---- 8-CTA barrier for this M-tile group (release-atomic, replay-safe) ----
        __syncthreads();
        if (tid == 0) {
            unsigned a;
            asm volatile("atom.add.release.gpu.u32 %0, [%1], 1;"
                         : "=r"(a) : "l"(&g_cnt[mt]));
            a += 1u;
            unsigned tgt = (a + 7u) & ~7u;    // counter starts each replay == 0 (mod 8)
            unsigned v;
            do {
                asm volatile("ld.global.acquire.gpu.u32 %0, [%1];"
                             : "=r"(v) : "l"(&g_cnt[mt]));
            } while (v < tgt);
        }
        __syncthreads();
    }
}

extern "C" void kernel_launch(void* const* d_in, const int* in_sizes, int n_in,
                              void* d_out, int out_size)
{
    const int*   trans  = (const int*)  d_in[0];
    const int*   labels = (const int*)  d_in[1];
    const float* emb    = (const float*)d_in[2];
    const float* W      = (const float*)d_in[3];
    const float* b      = (const float*)d_in[4];
    const float* leaf   = (const float*)d_in[5];
    float*       out    = (float*)d_out;

    cudaFuncSetAttribute(spinn_persistent,
                         cudaFuncAttributeMaxDynamicSharedMemorySize, SMEM_BYTES);
    spinn_persistent<<<GRID, THREADS, SMEM_BYTES>>>(trans, labels, emb, W, b, leaf, out);
}

// round 5
// speedup vs baseline: 1.5966x; 1.1339x over previous
#include <cuda_runtime.h>
#include <math.h>

#define DD 512          // transition steps
#define NN 256          // batch
#define HH 128          // h_dim
#define LL 64           // label dim
#define KDIM 320        // L + 2H
#define NGATE 5
#define MT 16           // batch rows per CTA
#define HT 8            // h units per CTA (halved -> 2 CTAs/SM)
#define NMT (NN / MT)   // 16 M-tiles
#define NHG (HH / HT)   // 16 h-groups
#define GRID (NMT * NHG) // 256 CTAs
#define THREADS 256

#define WSM_F 12800       // 80 k4 * 5 g * 4 hcp * 8 floats
#define XROW  660         // padded X row stride in floats (dup layout: 640 used)
#define XSM_F (MT * XROW) // 10560 floats

// ---- device scratch (static module allocations, the sanctioned path) ----
__device__ float g_hst[(long)DD * NN * HH];   // h stack  [D][N][H]
__device__ float g_cst[(long)DD * NN * HH];   // c stack  [D][N][H]
__device__ unsigned g_cnt[NMT];               // per-M-tile barrier counters (monotonic)

__device__ __forceinline__ float sigf(float x) { return 1.0f / (1.0f + expf(-x)); }

// packed fp32x2 FMA (Blackwell FFMA2 — only reachable via PTX)
#define FMA2(d, a, b) asm("fma.rn.f32x2 %0, %1, %2, %0;" : "+l"(d) : "l"(a), "l"(b))

#define SMEM_BYTES ((WSM_F + XSM_F + NGATE * HT + HH) * 4 + 5 * MT * 4 + MT * DD * 2 + 64)

__global__ void __launch_bounds__(THREADS, 2) spinn_persistent(
    const int*   __restrict__ trans,     // [D][N]
    const int*   __restrict__ labels,    // [D][N]
    const float* __restrict__ emb,       // [V][L]
    const float* __restrict__ W,         // [320][640]
    const float* __restrict__ b,         // [640]
    const float* __restrict__ leaf,      // [128]
    float*       __restrict__ out)       // [2][N][H]  (c then h)
{
    extern __shared__ float sm[];
    float* Wsm = sm;                               // [80 k4][5 g][4 hcp][8]
    float* Xsm = sm + WSM_F;                       // dup layout [16 rows][660]
    float* bsm = Xsm + XSM_F;                      // [40]
    float* Lsm = bsm + NGATE * HT;                 // [128] leaf cache
    int*   ri_m   = (int*)(Lsm + HH);              // [MT] mask
    int*   ri_l   = ri_m + MT;                     // [MT] lidx
    int*   ri_r   = ri_l + MT;                     // [MT] ridx
    int*   ri_lab = ri_r + MT;                     // [MT] label idx
    int*   ssp    = ri_lab + MT;                   // [MT] stack ptr
    unsigned short* stk = (unsigned short*)(ssp + MT); // [MT][DD]

    const int tid = threadIdx.x;
    const int ci  = blockIdx.x;
    const int mt  = ci >> 4;          // M-tile 0..15
    const int hg  = ci & 15;          // h-group 0..15
    const int n0  = mt * MT;
    const int h0  = hg * HT;
    const int row = tid & 15;         // epilogue: batch row within tile
    const int hc  = tid >> 4;         // epilogue: h unit within tile (0..7), valid tid<128

    // GEMM thread geometry: rp = row-pair, hqp = hc-pair (1 of 4), ks = k-split (1 of 8)
    const int rp  = tid & 7;          // 0..7  -> rows 2rp, 2rp+1
    const int hqp = (tid >> 3) & 3;   // 0..3  -> hc 2hqp, 2hqp+1
    const int ks  = tid >> 5;         // 0..7  -> k4 in [ks*10, ks*10+10)

    // ---- one-time: W relayout into smem ----
    // Wsm[((k4*5+g)*4+hcp)*8 + kk*2 + lane] = W[(k4*4+kk)*640 + g*128 + h0 + hcp*2 + lane]
    for (int e = tid; e < WSM_F; e += THREADS) {
        int lane = e & 1;
        int kk   = (e >> 1) & 3;
        int hcp  = (e >> 3) & 3;
        int g    = (e >> 5) % 5;
        int k4   = e / 160;
        Wsm[e] = W[(long)(k4 * 4 + kk) * (NGATE * HH) + g * HH + h0 + hcp * 2 + lane];
    }
    if (tid < NGATE * HT) {
        int g = tid >> 3, hcc = tid & 7;
        bsm[tid] = b[g * HH + h0 + hcc];
    }
    if (tid < HH) Lsm[tid] = leaf[tid];
    if (tid < MT) ssp[tid] = 0;
    __syncthreads();

    for (int t = 0; t < DD; ++t) {
        // ---- stack simulation + row info (threads 0..15) ----
        if (tid < MT) {
            int n = n0 + tid;
            int m = trans[t * NN + n];
            ri_lab[tid] = labels[t * NN + n];
            int sp = ssp[tid];
            int li = 0, rx = 0;
            if (m) { rx = stk[tid * DD + sp - 1]; li = stk[tid * DD + sp - 2]; }
            ri_m[tid] = m; ri_l[tid] = li; ri_r[tid] = rx;
            int np = sp - 2 * m;
            stk[tid * DD + np] = (unsigned short)t;
            ssp[tid] = np + 1;
        }
        __syncthreads();

        // ---- gather X (value-duplicated float2) = [label|hl|hr] ----
        {
            float2* X2 = (float2*)Xsm;
            for (int e = tid; e < MT * LL; e += THREADS) {       // label embedding
                int r = e >> 6, k = e & 63;
                float v = emb[(long)ri_lab[r] * LL + k];
                X2[r * (XROW / 2) + k] = make_float2(v, v);
            }
            for (int e = tid; e < MT * HH; e += THREADS) {       // h_left
                int r = e >> 7, k = e & 127;
                float v = ri_m[r] ? __ldcg(&g_hst[((long)ri_l[r] * NN + n0 + r) * HH + k])
                                  : Lsm[k];
                X2[r * (XROW / 2) + LL + k] = make_float2(v, v);
            }
            for (int e = tid; e < MT * HH; e += THREADS) {       // h_right
                int r = e >> 7, k = e & 127;
                float v = ri_m[r] ? __ldcg(&g_hst[((long)ri_r[r] * NN + n0 + r) * HH + k])
                                  : Lsm[k];
                X2[r * (XROW / 2) + LL + HH + k] = make_float2(v, v);
            }
        }
        __syncthreads();

        // ---- GEMM slice: 2 rows x 5 gates x (2 hc packed), k in [ks*40, ks*40+40) ----
        long long acc[10];
        #pragma unroll
        for (int a = 0; a < 10; ++a) acc[a] = 0;   // f32x2 (0.0f, 0.0f)

        const longlong2* Xr0 = (const longlong2*)(Xsm + (2 * rp)     * XROW);
        const longlong2* Xr1 = (const longlong2*)(Xsm + (2 * rp + 1) * XROW);
        const int k4base = ks * 10;

        #pragma unroll 2
        for (int i = 0; i < 10; ++i) {
            int k4 = k4base + i;
            longlong2 xa0 = Xr0[k4 * 2];       // dup(x_k0), dup(x_k1)  (row A)
            longlong2 xa1 = Xr0[k4 * 2 + 1];   // dup(x_k2), dup(x_k3)
            longlong2 xb0 = Xr1[k4 * 2];
            longlong2 xb1 = Xr1[k4 * 2 + 1];
            const float* wb = Wsm + k4 * 160 + hqp * 8;
            #pragma unroll
            for (int g = 0; g < 5; ++g) {
                longlong2 w01 = *(const longlong2*)(wb + g * 32);       // (h0,h1)@k0, @k1
                longlong2 w23 = *(const longlong2*)(wb + g * 32 + 4);   // (h0,h1)@k2, @k3
                FMA2(acc[g],     xa0.x, w01.x);
                FMA2(acc[g],     xa0.y, w01.y);
                FMA2(acc[g],     xa1.x, w23.x);
                FMA2(acc[g],     xa1.y, w23.y);
                FMA2(acc[5 + g], xb0.x, w01.x);
                FMA2(acc[5 + g], xb0.y, w01.y);
                FMA2(acc[5 + g], xb1.x, w23.x);
                FMA2(acc[5 + g], xb1.y, w23.y);
            }
        }
        __syncthreads();   // all X reads done; reuse X region for partials

        // ---- write k-split partials: Red[ks][rp][hqp][10] (f32x2) ----
        {
            long long* Red = (long long*)Xsm;
            long long* dst = Red + (((ks * 8 + rp) * 4 + hqp) * 10);
            #pragma unroll
            for (int a = 0; a < 10; ++a) dst[a] = acc[a];
        }
        __syncthreads();

        // ---- reduce + gates + cell update: thread = (row, hc), tid < 128 ----
        if (tid < MT * HT) {
            const float* Redf = Xsm;
            // partial float idx = ((ks*8+rp)*4+hqp)*20 + (r*5+g)*2 + lane
            const int base0 = (((row >> 1) * 4 + (hc >> 1)) * 10 + (row & 1) * 5) * 2 + (hc & 1);
            float gate[5];
            #pragma unroll
            for (int g = 0; g < 5; ++g) {
                int f = base0 + g * 2;
                float s = 0.f;
                #pragma unroll
                for (int kq = 0; kq < 8; ++kq) s += Redf[f + kq * 640];
                gate[g] = s + bsm[g * HT + hc];
            }
            int n = n0 + row;
            int h = h0 + hc;
            int m = ri_m[row];
            float cl = m ? __ldcg(&g_cst[((long)ri_l[row] * NN + n) * HH + h]) : Lsm[h];
            float cr = m ? __ldcg(&g_cst[((long)ri_r[row] * NN + n) * HH + h]) : Lsm[h];
            float c  = sigf(gate[0]) * tanhf(gate[4]) + sigf(gate[1]) * cl + sigf(gate[2]) * cr;
            float hv = sigf(gate[3]) * tanhf(c);
            long off = ((long)t * NN + n) * HH + h;
            g_cst[off] = c;
            g_hst[off] = hv;
            if (t == DD - 1) {
                out[n * HH + h] = c;                  // c_st[D-1] first
                out[NN * HH + n * HH + h] = hv;       // then h_st[D-1]
            }
        }

        // ---- 16-CTA barrier for this M-tile group (release-atomic, replay-safe) ----
        __syncthreads();
        if (tid == 0) {
            unsigned a;
            asm volatile("atom.add.release.gpu.u32 %0, [%1], 1;"
                         : "=r"(a) : "l"(&g_cnt[mt]));
            a += 1u;
            unsigned tgt = (a + 15u) & ~15u;   // counter starts each replay == 0 (mod 16)
            unsigned v;
            do {
                asm volatile("ld.global.acquire.gpu.u32 %0, [%1];"
                             : "=r"(v) : "l"(&g_cnt[mt]));
            } while (v < tgt);
        }
        __syncthreads();
    }
}

extern "C" void kernel_launch(void* const* d_in, const int* in_sizes, int n_in,
                              void* d_out, int out_size)
{
    const int*   trans  = (const int*)  d_in[0];
    const int*   labels = (const int*)  d_in[1];
    const float* emb    = (const float*)d_in[2];
    const float* W      = (const float*)d_in[3];
    const float* b      = (const float*)d_in[4];
    const float* leaf   = (const float*)d_in[5];
    float*       out    = (float*)d_out;

    cudaFuncSetAttribute(spinn_persistent,
                         cudaFuncAttributeMaxDynamicSharedMemorySize, SMEM_BYTES);
    spinn_persistent<<<GRID, THREADS, SMEM_BYTES>>>(trans, labels, emb, W, b, leaf, out);
}